// round 3
// baseline (speedup 1.0000x reference)
#include <cuda_runtime.h>
#include <math.h>

#define HID 300
#define NNODES 80000
#define NEDGES 160000
#define HALF 80000
#define NGRAPHS 1600
#define NODE_DIM 133
#define EDGE_DIM 14

// ---------------- scratch ----------------
__device__ float g_h  [NEDGES * HID];
__device__ float g_h2 [NEDGES * HID];
__device__ float g_inc[NNODES * HID];
__device__ float g_shared[NNODES * HID];
__device__ float g_mu [NNODES * HID];
__device__ float g_lv [NNODES * HID];
__device__ float g_mug[NGRAPHS * HID];
__device__ float g_lvg[NGRAPHS * HID];
__device__ float g_cnt[NGRAPHS];

// edge index helpers: src = cat(src_half, dst_half), dst = cat(dst_half, src_half)
__device__ __forceinline__ int e_src(int e, const int* sh, const int* dh) {
    return e < HALF ? sh[e] : dh[e - HALF];
}
__device__ __forceinline__ int e_dst(int e, const int* sh, const int* dh) {
    return e < HALF ? dh[e] : sh[e - HALF];
}
__device__ __forceinline__ int e_rev(int e) {
    return e < HALF ? e + HALF : e - HALF;
}

// ---------------- tiled SGEMM with fused gather A ----------------
// C[M, 300] = A[M, K] @ W[K, 300] (+ bias, + optional residual/relu)
// Block tile 128x64, thread tile 8x4, 256 threads, BK=16.
// MODE 0 (edge lin):  A[e][k] = k<IN ? A1[src(e)*IN + k] : A2[e*EDGE_DIM + k-IN]
// MODE 1 (mp step):   A[e][k] = A1[src(e)*HID + k] - A2[rev(e)*HID + k]
//                     epilogue: C = relu(A2[e][c] + acc + bias)
// MODE 2 (atom upd):  A[n][k] = k<IN ? A1[n*IN + k] : A2[n*HID + k-IN]
template <int MODE>
__global__ __launch_bounds__(256)
void gemm_kernel(const float* __restrict__ A1,
                 const float* __restrict__ A2,
                 const float* __restrict__ W,
                 const float* __restrict__ bias,
                 const int* __restrict__ sh,
                 const int* __restrict__ dh,
                 float* __restrict__ C,
                 int M, int K, int IN, int do_relu) {
    __shared__ float As[16][132];   // [k][row], padded stride
    __shared__ float Bs[16][64];    // [k][col]

    const int bm = blockIdx.x * 128;
    const int bn = blockIdx.y * 64;
    const int tid = threadIdx.x;
    const int tx = tid & 15;          // output col group (x4)
    const int ty = tid >> 4;          // output row group (x8)

    // A-load mapping: one k per thread, 8 consecutive rows
    const int la_k  = tid & 15;
    const int la_r0 = (tid >> 4) * 8;
    // B-load mapping: one k-row, 4 consecutive cols
    const int lb_k = tid >> 4;
    const int lb_c = (tid & 15) * 4;

    // Hoist row-dependent gather offsets out of the k-loop
    int offA[8], offB[8];
#pragma unroll
    for (int j = 0; j < 8; j++) {
        const int row = bm + la_r0 + j;
        if (MODE == 0) {
            offA[j] = e_src(row, sh, dh) * IN;
            offB[j] = row * EDGE_DIM;
        } else if (MODE == 1) {
            offA[j] = e_src(row, sh, dh) * HID;
            offB[j] = e_rev(row) * HID;
        } else {
            offA[j] = row * IN;
            offB[j] = row * HID;
        }
    }

    float acc[8][4];
#pragma unroll
    for (int i = 0; i < 8; i++)
#pragma unroll
        for (int j = 0; j < 4; j++) acc[i][j] = 0.f;

    for (int k0 = 0; k0 < K; k0 += 16) {
        // ---- load A tile (gathered, coalesced along k within each row)
        {
            const int gk = k0 + la_k;
            const bool kv = gk < K;
#pragma unroll
            for (int j = 0; j < 8; j++) {
                float v = 0.f;
                if (kv) {
                    if (MODE == 1) {
                        v = A1[offA[j] + gk] - A2[offB[j] + gk];
                    } else {
                        v = (gk < IN) ? A1[offA[j] + gk]
                                      : A2[offB[j] + (gk - IN)];
                    }
                }
                As[la_k][la_r0 + j] = v;
            }
        }
        // ---- load B tile
        {
            const int gk = k0 + lb_k;
            float4 bv = make_float4(0.f, 0.f, 0.f, 0.f);
            if (gk < K) {
                const int gc = bn + lb_c;
                if (gc + 3 < HID) {
                    bv = *reinterpret_cast<const float4*>(&W[gk * HID + gc]);
                } else {
                    float t0 = (gc + 0 < HID) ? W[gk * HID + gc + 0] : 0.f;
                    float t1 = (gc + 1 < HID) ? W[gk * HID + gc + 1] : 0.f;
                    float t2 = (gc + 2 < HID) ? W[gk * HID + gc + 2] : 0.f;
                    float t3 = (gc + 3 < HID) ? W[gk * HID + gc + 3] : 0.f;
                    bv = make_float4(t0, t1, t2, t3);
                }
            }
            *reinterpret_cast<float4*>(&Bs[lb_k][lb_c]) = bv;
        }
        __syncthreads();

#pragma unroll
        for (int kk = 0; kk < 16; kk++) {
            const float4 a0 = *reinterpret_cast<const float4*>(&As[kk][ty * 8]);
            const float4 a1 = *reinterpret_cast<const float4*>(&As[kk][ty * 8 + 4]);
            const float4 bv = *reinterpret_cast<const float4*>(&Bs[kk][tx * 4]);
            const float a[8] = {a0.x, a0.y, a0.z, a0.w, a1.x, a1.y, a1.z, a1.w};
            const float b[4] = {bv.x, bv.y, bv.z, bv.w};
#pragma unroll
            for (int i = 0; i < 8; i++)
#pragma unroll
                for (int j = 0; j < 4; j++) acc[i][j] += a[i] * b[j];
        }
        __syncthreads();
    }

    // ---- epilogue
    const int gc0 = bn + tx * 4;
    float bs[4];
#pragma unroll
    for (int j = 0; j < 4; j++) bs[j] = (gc0 + j < HID) ? bias[gc0 + j] : 0.f;

#pragma unroll
    for (int i = 0; i < 8; i++) {
        const int row = bm + ty * 8 + i;   // M is a multiple of 128: no row guard
        float v[4];
#pragma unroll
        for (int j = 0; j < 4; j++) v[j] = acc[i][j] + bs[j];
        if (MODE == 1) {
            if (gc0 + 3 < HID) {
                const float4 r = *reinterpret_cast<const float4*>(&A2[row * HID + gc0]);
                v[0] = fmaxf(v[0] + r.x, 0.f);
                v[1] = fmaxf(v[1] + r.y, 0.f);
                v[2] = fmaxf(v[2] + r.z, 0.f);
                v[3] = fmaxf(v[3] + r.w, 0.f);
                *reinterpret_cast<float4*>(&C[row * HID + gc0]) =
                    make_float4(v[0], v[1], v[2], v[3]);
            } else {
#pragma unroll
                for (int j = 0; j < 4; j++) {
                    if (gc0 + j < HID) {
                        float vv = fmaxf(v[j] + A2[row * HID + gc0 + j], 0.f);
                        C[row * HID + gc0 + j] = vv;
                    }
                }
            }
        } else {
            if (do_relu) {
#pragma unroll
                for (int j = 0; j < 4; j++) v[j] = fmaxf(v[j], 0.f);
            }
            if (gc0 + 3 < HID) {
                *reinterpret_cast<float4*>(&C[row * HID + gc0]) =
                    make_float4(v[0], v[1], v[2], v[3]);
            } else {
#pragma unroll
                for (int j = 0; j < 4; j++)
                    if (gc0 + j < HID) C[row * HID + gc0 + j] = v[j];
            }
        }
    }
}

// ---------------- segment sum over edges: inc[dst(e)] += h[e] ----------------
__global__ void segsum_kernel(const float* __restrict__ h,
                              float* __restrict__ inc,
                              const int* __restrict__ sh,
                              const int* __restrict__ dh) {
    const int idx = blockIdx.x * blockDim.x + threadIdx.x;
    const int e = idx / 75;         // 300/4 float4 chunks
    const int ch = idx % 75;
    if (e >= NEDGES) return;
    const int d = e_dst(e, sh, dh);
    const float4 v = *reinterpret_cast<const float4*>(&h[e * HID + ch * 4]);
    float* base = &inc[d * HID + ch * 4];
    atomicAdd(base + 0, v.x);
    atomicAdd(base + 1, v.y);
    atomicAdd(base + 2, v.z);
    atomicAdd(base + 3, v.w);
}

__global__ void zero_kernel(float4* __restrict__ p, long n4) {
    long i = (long)blockIdx.x * blockDim.x + threadIdx.x;
    if (i < n4) p[i] = make_float4(0.f, 0.f, 0.f, 0.f);
}

// ---------------- graph pooling ----------------
__global__ void pool_cnt_kernel(const int* __restrict__ batch) {
    const int n = blockIdx.x * blockDim.x + threadIdx.x;
    if (n >= NNODES) return;
    atomicAdd(&g_cnt[batch[n]], 1.f);
}

__global__ void pool_acc_kernel(const float* __restrict__ mu,
                                const float* __restrict__ lv,
                                const float* __restrict__ W_atoms,
                                const int* __restrict__ batch) {
    const int idx = blockIdx.x * blockDim.x + threadIdx.x;
    const int n = idx / 75;
    const int ch = idx % 75;
    if (n >= NNODES) return;
    const float w = W_atoms[n];
    const int b = batch[n];
    const float4 m = *reinterpret_cast<const float4*>(&mu[n * HID + ch * 4]);
    const float4 l = *reinterpret_cast<const float4*>(&lv[n * HID + ch * 4]);
    float* mb = &g_mug[b * HID + ch * 4];
    float* lb = &g_lvg[b * HID + ch * 4];
    atomicAdd(mb + 0, m.x * w); atomicAdd(mb + 1, m.y * w);
    atomicAdd(mb + 2, m.z * w); atomicAdd(mb + 3, m.w * w);
    atomicAdd(lb + 0, l.x * w); atomicAdd(lb + 1, l.y * w);
    atomicAdd(lb + 2, l.z * w); atomicAdd(lb + 3, l.w * w);
}

__global__ void finalize_kernel(const float* __restrict__ eps,
                                float* __restrict__ out) {
    const int idx = blockIdx.x * blockDim.x + threadIdx.x;
    if (idx >= NGRAPHS * HID) return;
    const int g = idx / HID;
    const float c = fmaxf(g_cnt[g], 1.f);
    const float mug = g_mug[idx] / c;
    const float lvg = g_lvg[idx] / c;
    out[idx] = mug + expf(0.5f * lvg) * eps[idx];
}

// ---------------- host side ----------------
static float* sym_addr(const void* s) {
    void* p = nullptr;
    cudaGetSymbolAddress(&p, s);
    return (float*)p;
}

static void launch_zero(float* p, long n) {   // n must be multiple of 4 (it is: *300)
    long n4 = n / 4;
    int threads = 256;
    long blocks = (n4 + threads - 1) / threads;
    zero_kernel<<<(unsigned)blocks, threads>>>((float4*)p, n4);
}

extern "C" void kernel_launch(void* const* d_in, const int* in_sizes, int n_in,
                              void* d_out, int out_size) {
    const float* x         = (const float*)d_in[0];
    const float* edge_attr = (const float*)d_in[1];
    const float* W_atoms   = (const float*)d_in[2];
    const float* eps       = (const float*)d_in[3];
    const int*   src_half  = (const int*)d_in[4];
    const int*   dst_half  = (const int*)d_in[5];
    const int*   batch     = (const int*)d_in[6];
    const float* t_lin_w = (const float*)d_in[7];
    const float* t_lin_b = (const float*)d_in[8];
    const float* t_mp_w  = (const float*)d_in[9];
    const float* t_mp_b  = (const float*)d_in[10];
    const float* t_au_w  = (const float*)d_in[11];
    const float* t_au_b  = (const float*)d_in[12];
    const float* mu_lin_w = (const float*)d_in[13];
    const float* mu_lin_b = (const float*)d_in[14];
    const float* mu_mp_w  = (const float*)d_in[15];
    const float* mu_mp_b  = (const float*)d_in[16];
    const float* mu_au_w  = (const float*)d_in[17];
    const float* mu_au_b  = (const float*)d_in[18];
    const float* lv_lin_w = (const float*)d_in[19];
    const float* lv_lin_b = (const float*)d_in[20];
    const float* lv_mp_w  = (const float*)d_in[21];
    const float* lv_mp_b  = (const float*)d_in[22];
    const float* lv_au_w  = (const float*)d_in[23];
    const float* lv_au_b  = (const float*)d_in[24];

    float* h      = sym_addr(g_h);
    float* h2     = sym_addr(g_h2);
    float* inc    = sym_addr(g_inc);
    float* shared = sym_addr(g_shared);
    float* mu     = sym_addr(g_mu);
    float* lv     = sym_addr(g_lv);
    float* mug    = sym_addr(g_mug);
    float* lvg    = sym_addr(g_lvg);
    float* cnt    = sym_addr(g_cnt);

    const int GT = 256;
    const int seg_blocks = (NEDGES * 75 + GT - 1) / GT;
    const int GRID_N = (HID + 63) / 64;   // 5

    auto conv = [&](const float* node_in, int IN,
                    const float* lin_w, const float* lin_b,
                    const float* mp_w, const float* mp_b,
                    const float* au_w, const float* au_b,
                    float* outp, int out_relu) {
        // edge linear: h = relu(cat(node_in[src], edge_attr) @ lin_w + b)
        {
            dim3 grid(NEDGES / 128, GRID_N);
            gemm_kernel<0><<<grid, 256>>>(node_in, edge_attr, lin_w, lin_b,
                                          src_half, dst_half, h,
                                          NEDGES, IN + EDGE_DIM, IN, 1);
        }
        float* hc = h;
        float* hn = h2;
        for (int i = 0; i < 3; i++) {
            launch_zero(inc, (long)NNODES * HID);
            segsum_kernel<<<seg_blocks, GT>>>(hc, inc, src_half, dst_half);
            dim3 grid(NEDGES / 128, GRID_N);
            gemm_kernel<1><<<grid, 256>>>(inc, hc,
                                          mp_w + (long)i * HID * HID,
                                          mp_b + i * HID,
                                          src_half, dst_half, hn,
                                          NEDGES, HID, 0, 1);
            float* t = hc; hc = hn; hn = t;
        }
        // sum_inc for atom update
        launch_zero(inc, (long)NNODES * HID);
        segsum_kernel<<<seg_blocks, GT>>>(hc, inc, src_half, dst_half);
        {
            dim3 grid(NNODES / 128, GRID_N);
            gemm_kernel<2><<<grid, 256>>>(node_in, inc, au_w, au_b,
                                          src_half, dst_half, outp,
                                          NNODES, IN + HID, IN, out_relu);
        }
    };

    conv(x, NODE_DIM, t_lin_w, t_lin_b, t_mp_w, t_mp_b, t_au_w, t_au_b, shared, 1);
    conv(shared, HID, mu_lin_w, mu_lin_b, mu_mp_w, mu_mp_b, mu_au_w, mu_au_b, mu, 0);
    conv(shared, HID, lv_lin_w, lv_lin_b, lv_mp_w, lv_mp_b, lv_au_w, lv_au_b, lv, 0);

    // pooling + reparameterization
    launch_zero(mug, (long)NGRAPHS * HID);
    launch_zero(lvg, (long)NGRAPHS * HID);
    zero_kernel<<<(NGRAPHS / 4 + GT - 1) / GT, GT>>>((float4*)cnt, NGRAPHS / 4);
    pool_cnt_kernel<<<(NNODES + GT - 1) / GT, GT>>>(batch);
    pool_acc_kernel<<<(NNODES * 75 + GT - 1) / GT, GT>>>(mu, lv, W_atoms, batch);
    finalize_kernel<<<(NGRAPHS * HID + GT - 1) / GT, GT>>>(eps, (float*)d_out);
}

// round 13
// speedup vs baseline: 2.2905x; 2.2905x over previous
#include <cuda_runtime.h>
#include <cuda_bf16.h>
#include <math.h>
#include <stdint.h>

#define HID 300
#define NNODES 80000
#define NEDGES 160000
#define HALF 80000
#define NGRAPHS 1600
#define NODE_DIM 133
#define EDGE_DIM 14

// ---------------- scratch ----------------
__device__ float g_h  [NEDGES * HID];
__device__ float g_h2 [NEDGES * HID];
__device__ float g_inc[NNODES * HID];
__device__ float g_shared[NNODES * HID];
__device__ float g_mu [NNODES * HID];
__device__ float g_lv [NNODES * HID];
__device__ float g_mug[NGRAPHS * HID];
__device__ float g_lvg[NGRAPHS * HID];
__device__ float g_cnt[NGRAPHS];
__device__ __nv_bfloat16 g_wbhi[600 * HID];   // W hi (bf16), [K][300]
__device__ __nv_bfloat16 g_wblo[600 * HID];   // W lo (residual bf16)

// ---------------- helpers ----------------
__device__ __forceinline__ uint32_t smem_u32(const void* p) {
    uint32_t a;
    asm("{ .reg .u64 t; cvta.to.shared.u64 t, %1; cvt.u32.u64 %0, t; }" : "=r"(a) : "l"(p));
    return a;
}

#define LDSM4(r, addr) \
    asm volatile("ldmatrix.sync.aligned.m8n8.x4.shared.b16 {%0,%1,%2,%3}, [%4];" \
                 : "=r"((r)[0]), "=r"((r)[1]), "=r"((r)[2]), "=r"((r)[3]) : "r"(addr))
#define LDSM4T(r, addr) \
    asm volatile("ldmatrix.sync.aligned.m8n8.x4.trans.shared.b16 {%0,%1,%2,%3}, [%4];" \
                 : "=r"((r)[0]), "=r"((r)[1]), "=r"((r)[2]), "=r"((r)[3]) : "r"(addr))
#define MMA16816(d, a, b0, b1) \
    asm volatile("mma.sync.aligned.m16n8k16.row.col.f32.bf16.bf16.f32 " \
                 "{%0,%1,%2,%3}, {%4,%5,%6,%7}, {%8,%9}, {%0,%1,%2,%3};" \
                 : "+f"((d)[0]), "+f"((d)[1]), "+f"((d)[2]), "+f"((d)[3]) \
                 : "r"((a)[0]), "r"((a)[1]), "r"((a)[2]), "r"((a)[3]), "r"(b0), "r"(b1))

__device__ __forceinline__ uint32_t pack_bf2(__nv_bfloat16 l, __nv_bfloat16 h) {
    __nv_bfloat162 t;
    t.x = l; t.y = h;
    return *reinterpret_cast<uint32_t*>(&t);
}

__device__ __forceinline__ int e_src(int e, const int* sh, const int* dh) {
    return e < HALF ? sh[e] : dh[e - HALF];
}
__device__ __forceinline__ int e_dst(int e, const int* sh, const int* dh) {
    return e < HALF ? dh[e] : sh[e - HALF];
}
__device__ __forceinline__ int e_rev(int e) {
    return e < HALF ? e + HALF : e - HALF;
}

// ---------------- mma.sync bf16 3-pass GEMM with fused gather ----------------
// C[M,300] = A[M,K] @ W[K,300] (+bias, +residual/relu per MODE)
// MODE 0: A[e][k] = k<IN ? A1[src(e)*IN+k] : A2[e*EDGE_DIM + k-IN]
// MODE 1: A[e][k] = A1[src(e)*HID+k] - A2[rev(e)*HID+k]; epi: relu(acc+bias+A2[e][c])
// MODE 2: A[n][k] = k<IN ? A1[n*IN+k] : A2[n*HID + k-IN]
// grid = (5, M/128), 256 threads (8 warps, each 32x32 of the 128x64 tile)
#define BM 128
#define BN 64
#define BKH 32
#define ASTR 40   // halves per A smem row (32 + 8 pad) -> 80B stride
#define BSTR 72   // halves per B smem row (64 + 8 pad) -> 144B stride

template <int MODE>
__global__ __launch_bounds__(256)
void mma_gemm(const float* __restrict__ A1, const float* __restrict__ A2,
              const __nv_bfloat16* __restrict__ Whi,
              const __nv_bfloat16* __restrict__ Wlo,
              const float* __restrict__ bias,
              const int* __restrict__ sh, const int* __restrict__ dh,
              float* __restrict__ C, int K, int IN, int do_relu) {
    __shared__ __nv_bfloat16 Ash[BM * ASTR];
    __shared__ __nv_bfloat16 Asl[BM * ASTR];
    __shared__ __nv_bfloat16 Bsh[BKH * BSTR];
    __shared__ __nv_bfloat16 Bsl[BKH * BSTR];

    const int tid  = threadIdx.x;
    const int lane = tid & 31;
    const int wid  = tid >> 5;
    const int bn = blockIdx.x * BN;
    const int bm = blockIdx.y * BM;
    const int wm = (wid & 3) * 32;
    const int wn = (wid >> 2) * 32;

    // ---- A loader mapping: 2 threads per row, 16 k-halves each
    const int arow  = tid >> 1;
    const int akoff = (tid & 1) * 16;
    int offA, offB;
    {
        const int row = bm + arow;
        if (MODE == 1) {
            offA = e_src(row, sh, dh) * HID;
            offB = e_rev(row) * HID;
        } else if (MODE == 0) {
            offA = e_src(row, sh, dh) * IN;
            offB = row * EDGE_DIM;
        } else {
            offA = row * IN;
            offB = row * HID;
        }
    }
    // ---- B loader mapping: 8 threads per k-row, 8 n-halves each
    const int brow = tid >> 3;
    const int bcol = (tid & 7) * 8;

    float acc[2][4][4];
#pragma unroll
    for (int mi = 0; mi < 2; mi++)
#pragma unroll
        for (int ni = 0; ni < 4; ni++)
#pragma unroll
            for (int e = 0; e < 4; e++) acc[mi][ni][e] = 0.f;

    const int T = (K + BKH - 1) / BKH;
    for (int t = 0; t < T; t++) {
        const int k0 = t * BKH;
        // ---- gather A values in fp32
        float av[16];
        const int kg = k0 + akoff;
        if (MODE == 1) {
            if (kg + 15 < K) {
#pragma unroll
                for (int q = 0; q < 4; q++) {
                    const float4 a = *reinterpret_cast<const float4*>(&A1[offA + kg + q * 4]);
                    const float4 b = *reinterpret_cast<const float4*>(&A2[offB + kg + q * 4]);
                    av[q * 4 + 0] = a.x - b.x; av[q * 4 + 1] = a.y - b.y;
                    av[q * 4 + 2] = a.z - b.z; av[q * 4 + 3] = a.w - b.w;
                }
            } else {
#pragma unroll
                for (int j = 0; j < 16; j++) {
                    const int k = kg + j;
                    av[j] = (k < K) ? A1[offA + k] - A2[offB + k] : 0.f;
                }
            }
        } else {
#pragma unroll
            for (int j = 0; j < 16; j++) {
                const int k = kg + j;
                float v = 0.f;
                if (k < K) v = (k < IN) ? __ldg(&A1[offA + k]) : __ldg(&A2[offB + k - IN]);
                av[j] = v;
            }
        }
        // ---- split + pack + store A
        uint32_t ph[8], pl[8];
#pragma unroll
        for (int j = 0; j < 8; j++) {
            const __nv_bfloat16 h0 = __float2bfloat16_rn(av[2 * j]);
            const __nv_bfloat16 h1 = __float2bfloat16_rn(av[2 * j + 1]);
            const __nv_bfloat16 l0 = __float2bfloat16_rn(av[2 * j] - __bfloat162float(h0));
            const __nv_bfloat16 l1 = __float2bfloat16_rn(av[2 * j + 1] - __bfloat162float(h1));
            ph[j] = pack_bf2(h0, h1);
            pl[j] = pack_bf2(l0, l1);
        }
        {
            uint4* dh4 = reinterpret_cast<uint4*>(&Ash[arow * ASTR + akoff]);
            uint4* dl4 = reinterpret_cast<uint4*>(&Asl[arow * ASTR + akoff]);
            dh4[0] = make_uint4(ph[0], ph[1], ph[2], ph[3]);
            dh4[1] = make_uint4(ph[4], ph[5], ph[6], ph[7]);
            dl4[0] = make_uint4(pl[0], pl[1], pl[2], pl[3]);
            dl4[1] = make_uint4(pl[4], pl[5], pl[6], pl[7]);
        }
        // ---- B tile (bf16 hi/lo pre-split global, [K][300])
        {
            const int kgb = k0 + brow;
            const int n0 = bn + bcol;
            uint32_t bh[4], bl[4];
            if (kgb < K && n0 + 7 < HID) {
                const uint32_t* phg = reinterpret_cast<const uint32_t*>(&Whi[kgb * HID + n0]);
                const uint32_t* plg = reinterpret_cast<const uint32_t*>(&Wlo[kgb * HID + n0]);
#pragma unroll
                for (int q = 0; q < 4; q++) { bh[q] = phg[q]; bl[q] = plg[q]; }
            } else if (kgb < K) {
#pragma unroll
                for (int q = 0; q < 4; q++) {
                    const int na = n0 + 2 * q, nb = n0 + 2 * q + 1;
                    __nv_bfloat16 ha = (na < HID) ? Whi[kgb * HID + na] : __nv_bfloat16(0.f);
                    __nv_bfloat16 hb = (nb < HID) ? Whi[kgb * HID + nb] : __nv_bfloat16(0.f);
                    __nv_bfloat16 la = (na < HID) ? Wlo[kgb * HID + na] : __nv_bfloat16(0.f);
                    __nv_bfloat16 lb = (nb < HID) ? Wlo[kgb * HID + nb] : __nv_bfloat16(0.f);
                    bh[q] = pack_bf2(ha, hb);
                    bl[q] = pack_bf2(la, lb);
                }
            } else {
#pragma unroll
                for (int q = 0; q < 4; q++) { bh[q] = 0u; bl[q] = 0u; }
            }
            *reinterpret_cast<uint4*>(&Bsh[brow * BSTR + bcol]) = make_uint4(bh[0], bh[1], bh[2], bh[3]);
            *reinterpret_cast<uint4*>(&Bsl[brow * BSTR + bcol]) = make_uint4(bl[0], bl[1], bl[2], bl[3]);
        }
        __syncthreads();

        // ---- mma over 2 k16 steps
#pragma unroll
        for (int kk = 0; kk < 2; kk++) {
            uint32_t afh[2][4], afl[2][4];
#pragma unroll
            for (int mi = 0; mi < 2; mi++) {
                const int r = wm + mi * 16 + (lane & 15);
                const int c = kk * 16 + (lane >> 4) * 8;
                LDSM4(afh[mi], smem_u32(&Ash[r * ASTR + c]));
                LDSM4(afl[mi], smem_u32(&Asl[r * ASTR + c]));
            }
            uint32_t bfh[2][4], bfl[2][4];
#pragma unroll
            for (int nb = 0; nb < 2; nb++) {
                const int r = kk * 16 + (lane & 15);
                const int c = wn + nb * 16 + (lane >> 4) * 8;
                LDSM4T(bfh[nb], smem_u32(&Bsh[r * BSTR + c]));
                LDSM4T(bfl[nb], smem_u32(&Bsl[r * BSTR + c]));
            }
#pragma unroll
            for (int mi = 0; mi < 2; mi++)
#pragma unroll
                for (int ni = 0; ni < 4; ni++) {
                    const uint32_t* bh = &bfh[ni >> 1][(ni & 1) * 2];
                    const uint32_t* bl = &bfl[ni >> 1][(ni & 1) * 2];
                    MMA16816(acc[mi][ni], afh[mi], bh[0], bh[1]);
                    MMA16816(acc[mi][ni], afl[mi], bh[0], bh[1]);
                    MMA16816(acc[mi][ni], afh[mi], bl[0], bl[1]);
                }
        }
        __syncthreads();
    }

    // ---- epilogue
    const int r0 = bm + wm + (lane >> 2);
    const int c0 = bn + wn + (lane & 3) * 2;
#pragma unroll
    for (int mi = 0; mi < 2; mi++) {
#pragma unroll
        for (int ni = 0; ni < 4; ni++) {
            const int col = c0 + ni * 8;
            if (col >= HID) continue;
            const float b0 = __ldg(&bias[col]);
            const float b1 = __ldg(&bias[col + 1]);
#pragma unroll
            for (int half = 0; half < 2; half++) {
                const int row = r0 + mi * 16 + half * 8;
                float v0 = acc[mi][ni][half * 2 + 0] + b0;
                float v1 = acc[mi][ni][half * 2 + 1] + b1;
                if (MODE == 1) {
                    const float2 r2 = *reinterpret_cast<const float2*>(&A2[row * HID + col]);
                    v0 = fmaxf(v0 + r2.x, 0.f);
                    v1 = fmaxf(v1 + r2.y, 0.f);
                } else if (do_relu) {
                    v0 = fmaxf(v0, 0.f);
                    v1 = fmaxf(v1, 0.f);
                }
                *reinterpret_cast<float2*>(&C[row * HID + col]) = make_float2(v0, v1);
            }
        }
    }
}

// ---------------- W bf16 hi/lo split ----------------
__global__ void split_w(const float* __restrict__ W, int total) {
    const int idx = blockIdx.x * blockDim.x + threadIdx.x;
    if (idx >= total) return;
    const float v = W[idx];
    const __nv_bfloat16 h = __float2bfloat16_rn(v);
    g_wbhi[idx] = h;
    g_wblo[idx] = __float2bfloat16_rn(v - __bfloat162float(h));
}

// ---------------- segment sum: inc[dst(e)] += h[e] ----------------
__global__ void segsum_kernel(const float* __restrict__ h,
                              float* __restrict__ inc,
                              const int* __restrict__ sh,
                              const int* __restrict__ dh) {
    const int idx = blockIdx.x * blockDim.x + threadIdx.x;
    const int e = idx / 75;
    const int ch = idx % 75;
    if (e >= NEDGES) return;
    const int d = e_dst(e, sh, dh);
    const float4 v = *reinterpret_cast<const float4*>(&h[e * HID + ch * 4]);
    float* base = &inc[d * HID + ch * 4];
    atomicAdd(base + 0, v.x);
    atomicAdd(base + 1, v.y);
    atomicAdd(base + 2, v.z);
    atomicAdd(base + 3, v.w);
}

__global__ void zero_kernel(float4* __restrict__ p, long n4) {
    long i = (long)blockIdx.x * blockDim.x + threadIdx.x;
    if (i < n4) p[i] = make_float4(0.f, 0.f, 0.f, 0.f);
}

// ---------------- pooling ----------------
__global__ void pool_cnt_kernel(const int* __restrict__ batch) {
    const int n = blockIdx.x * blockDim.x + threadIdx.x;
    if (n >= NNODES) return;
    atomicAdd(&g_cnt[batch[n]], 1.f);
}

__global__ void pool_acc_kernel(const float* __restrict__ mu,
                                const float* __restrict__ lv,
                                const float* __restrict__ W_atoms,
                                const int* __restrict__ batch) {
    const int idx = blockIdx.x * blockDim.x + threadIdx.x;
    const int n = idx / 75;
    const int ch = idx % 75;
    if (n >= NNODES) return;
    const float w = W_atoms[n];
    const int b = batch[n];
    const float4 m = *reinterpret_cast<const float4*>(&mu[n * HID + ch * 4]);
    const float4 l = *reinterpret_cast<const float4*>(&lv[n * HID + ch * 4]);
    float* mb = &g_mug[b * HID + ch * 4];
    float* lb = &g_lvg[b * HID + ch * 4];
    atomicAdd(mb + 0, m.x * w); atomicAdd(mb + 1, m.y * w);
    atomicAdd(mb + 2, m.z * w); atomicAdd(mb + 3, m.w * w);
    atomicAdd(lb + 0, l.x * w); atomicAdd(lb + 1, l.y * w);
    atomicAdd(lb + 2, l.z * w); atomicAdd(lb + 3, l.w * w);
}

__global__ void finalize_kernel(const float* __restrict__ eps,
                                float* __restrict__ out) {
    const int idx = blockIdx.x * blockDim.x + threadIdx.x;
    if (idx >= NGRAPHS * HID) return;
    const int g = idx / HID;
    const float c = fmaxf(g_cnt[g], 1.f);
    out[idx] = g_mug[idx] / c + expf(0.5f * g_lvg[idx] / c) * eps[idx];
}

// ---------------- host ----------------
static float* sym_addr(const void* s) {
    void* p = nullptr;
    cudaGetSymbolAddress(&p, s);
    return (float*)p;
}
static void launch_zero(float* p, long n) {
    long n4 = n / 4;
    zero_kernel<<<(unsigned)((n4 + 255) / 256), 256>>>((float4*)p, n4);
}

extern "C" void kernel_launch(void* const* d_in, const int* in_sizes, int n_in,
                              void* d_out, int out_size) {
    const float* x         = (const float*)d_in[0];
    const float* edge_attr = (const float*)d_in[1];
    const float* W_atoms   = (const float*)d_in[2];
    const float* eps       = (const float*)d_in[3];
    const int*   src_half  = (const int*)d_in[4];
    const int*   dst_half  = (const int*)d_in[5];
    const int*   batch     = (const int*)d_in[6];
    const float* t_lin_w = (const float*)d_in[7];
    const float* t_lin_b = (const float*)d_in[8];
    const float* t_mp_w  = (const float*)d_in[9];
    const float* t_mp_b  = (const float*)d_in[10];
    const float* t_au_w  = (const float*)d_in[11];
    const float* t_au_b  = (const float*)d_in[12];
    const float* mu_lin_w = (const float*)d_in[13];
    const float* mu_lin_b = (const float*)d_in[14];
    const float* mu_mp_w  = (const float*)d_in[15];
    const float* mu_mp_b  = (const float*)d_in[16];
    const float* mu_au_w  = (const float*)d_in[17];
    const float* mu_au_b  = (const float*)d_in[18];
    const float* lv_lin_w = (const float*)d_in[19];
    const float* lv_lin_b = (const float*)d_in[20];
    const float* lv_mp_w  = (const float*)d_in[21];
    const float* lv_mp_b  = (const float*)d_in[22];
    const float* lv_au_w  = (const float*)d_in[23];
    const float* lv_au_b  = (const float*)d_in[24];

    float* h      = sym_addr(g_h);
    float* h2     = sym_addr(g_h2);
    float* inc    = sym_addr(g_inc);
    float* shared = sym_addr(g_shared);
    float* mu     = sym_addr(g_mu);
    float* lv     = sym_addr(g_lv);
    float* mug    = sym_addr(g_mug);
    float* lvg    = sym_addr(g_lvg);
    float* cnt    = sym_addr(g_cnt);
    const __nv_bfloat16* wbhi = (const __nv_bfloat16*)sym_addr(g_wbhi);
    const __nv_bfloat16* wblo = (const __nv_bfloat16*)sym_addr(g_wblo);

    const int GT = 256;
    const int seg_blocks = (NEDGES * 75 + GT - 1) / GT;
    const int GRID_N = 5;   // 5 x 64 >= 300

    auto split = [&](const float* w, int K) {
        const int total = K * HID;
        split_w<<<(total + GT - 1) / GT, GT>>>(w, total);
    };

    auto conv = [&](const float* node_in, int IN,
                    const float* lin_w, const float* lin_b,
                    const float* mp_w, const float* mp_b,
                    const float* au_w, const float* au_b,
                    float* outp, int out_relu) {
        // edge linear
        {
            const int K = IN + EDGE_DIM;
            split(lin_w, K);
            mma_gemm<0><<<dim3(GRID_N, NEDGES / BM), 256>>>(
                node_in, edge_attr, wbhi, wblo, lin_b,
                src_half, dst_half, h, K, IN, 1);
        }
        float* hc = h;
        float* hn = h2;
        for (int i = 0; i < 3; i++) {
            launch_zero(inc, (long)NNODES * HID);
            segsum_kernel<<<seg_blocks, GT>>>(hc, inc, src_half, dst_half);
            split(mp_w + (long)i * HID * HID, HID);
            mma_gemm<1><<<dim3(GRID_N, NEDGES / BM), 256>>>(
                inc, hc, wbhi, wblo, mp_b + i * HID,
                src_half, dst_half, hn, HID, 0, 1);
            float* t = hc; hc = hn; hn = t;
        }
        launch_zero(inc, (long)NNODES * HID);
        segsum_kernel<<<seg_blocks, GT>>>(hc, inc, src_half, dst_half);
        {
            const int K = IN + HID;
            split(au_w, K);
            mma_gemm<2><<<dim3(GRID_N, NNODES / BM), 256>>>(
                node_in, inc, wbhi, wblo, au_b,
                src_half, dst_half, outp, K, IN, out_relu);
        }
    };

    conv(x, NODE_DIM, t_lin_w, t_lin_b, t_mp_w, t_mp_b, t_au_w, t_au_b, shared, 1);
    conv(shared, HID, mu_lin_w, mu_lin_b, mu_mp_w, mu_mp_b, mu_au_w, mu_au_b, mu, 0);
    conv(shared, HID, lv_lin_w, lv_lin_b, lv_mp_w, lv_mp_b, lv_au_w, lv_au_b, lv, 0);

    // pooling + reparameterization
    launch_zero(mug, (long)NGRAPHS * HID);
    launch_zero(lvg, (long)NGRAPHS * HID);
    launch_zero(cnt, NGRAPHS);   // FIX: was <<<1,256>> covering only 256 of 400 float4s
    pool_cnt_kernel<<<(NNODES + GT - 1) / GT, GT>>>(batch);
    pool_acc_kernel<<<(NNODES * 75 + GT - 1) / GT, GT>>>(mu, lv, W_atoms, batch);
    finalize_kernel<<<(NGRAPHS * HID + GT - 1) / GT, GT>>>(eps, (float*)d_out);
}